// round 10
// baseline (speedup 1.0000x reference)
#include <cuda_runtime.h>
#include <cuda_bf16.h>
#include <cstdint>

#define NN 262144
#define NE 1048576
#define NG 8192
#define IN_CH 64
#define HID 256
#define SLOPE 0.1f

// ---------------- scratch (static device memory) ----------------
__device__ __align__(256) __nv_bfloat16 g_hbh[2][(size_t)NN * HID];
__device__ __align__(256) __nv_bfloat16 g_hbl[2][(size_t)NN * HID];
__device__ __align__(256) __nv_bfloat16 g_aggh[(size_t)NN * HID];
__device__ __align__(256) __nv_bfloat16 g_aggl[(size_t)NN * HID];
__device__ __align__(256) __nv_bfloat16 g_xh[(size_t)NN * IN_CH];
__device__ __align__(256) __nv_bfloat16 g_xl[(size_t)NN * IN_CH];
__device__ __align__(256) __nv_bfloat16 g_wlh[HID * HID];
__device__ __align__(256) __nv_bfloat16 g_wll[HID * HID];
__device__ __align__(256) __nv_bfloat16 g_wrh[HID * HID];
__device__ __align__(256) __nv_bfloat16 g_wrl[HID * HID];
__device__ __align__(256) __nv_bfloat16 g_weh[HID * IN_CH];
__device__ __align__(256) __nv_bfloat16 g_wel[HID * IN_CH];
__device__ __align__(256) float g_pooled[NG * HID];
__device__ __align__(256) float g_invdeg[NN];
__device__ __align__(256) int   g_deg[NN];
__device__ __align__(256) int   g_rowstart[NN + 1];
__device__ __align__(256) int   g_cursor[NN];
__device__ __align__(256) int   g_csr[NE];
__device__ __align__(256) int   g_blocksum[256];
__device__ __align__(256) int   g_blockoff[256];
__device__ __align__(256) int   g_bi[NN];
__device__ int g_ei64;
__device__ int g_b64;

// ---------------- PTX helpers (sm_80+ only) ----------------
__device__ __forceinline__ uint32_t smem_u32(const void* p) {
    uint32_t a;
    asm("{ .reg .u64 t; cvta.to.shared.u64 t, %1; cvt.u32.u64 %0, t; }" : "=r"(a) : "l"(p));
    return a;
}
#define CP_ASYNC16(dst, src) \
    asm volatile("cp.async.cg.shared.global [%0], [%1], 16;" :: "r"(dst), "l"(src) : "memory")
#define CP_COMMIT() asm volatile("cp.async.commit_group;" ::: "memory")
#define CP_WAIT1()  asm volatile("cp.async.wait_group 1;" ::: "memory")
#define CP_WAIT0()  asm volatile("cp.async.wait_group 0;" ::: "memory")

__device__ __forceinline__ void ldsm_x4(uint32_t r[4], uint32_t addr) {
    asm volatile("ldmatrix.sync.aligned.m8n8.x4.shared.b16 {%0,%1,%2,%3}, [%4];"
        : "=r"(r[0]), "=r"(r[1]), "=r"(r[2]), "=r"(r[3]) : "r"(addr));
}
__device__ __forceinline__ void mma_bf16(float& c0, float& c1, float& c2, float& c3,
                                         const uint32_t a[4], const uint32_t* b) {
    asm volatile("mma.sync.aligned.m16n8k16.row.col.f32.bf16.bf16.f32 "
        "{%0,%1,%2,%3}, {%4,%5,%6,%7}, {%8,%9}, {%0,%1,%2,%3};"
        : "+f"(c0), "+f"(c1), "+f"(c2), "+f"(c3)
        : "r"(a[0]), "r"(a[1]), "r"(a[2]), "r"(a[3]), "r"(b[0]), "r"(b[1]));
}

// ---------------- dtype detection ----------------
__global__ void k_detect(const int* __restrict__ ei32, const int* __restrict__ b32) {
    if (threadIdx.x == 0) {
        int is64 = 1;
        for (int i = 0; i < 64; i++)
            if (ei32[2 * i + 1] != 0) { is64 = 0; break; }
        g_ei64 = is64;
        int b64 = 1;
        for (int i = 0; i < 64; i++)
            if (b32[NN / 2 + 2 * i + 1] != 0) { b64 = 0; break; }
        g_b64 = b64;
    }
}
__device__ __forceinline__ int load_idx(const void* p, int idx, int is64) {
    if (is64) return (int)((const long long*)p)[idx];
    return ((const int*)p)[idx];
}

// ---------------- fp32 -> bf16 hi/lo split ----------------
__device__ __forceinline__ void split_bf16(float x, __nv_bfloat16& hi, __nv_bfloat16& lo) {
    hi = __float2bfloat16(x);
    lo = __float2bfloat16(x - __bfloat162float(hi));
}

// ---------------- x split ----------------
__global__ void k_xsplit(const float* __restrict__ x) {
    int t = blockIdx.x * 256 + threadIdx.x;
    float4 v = *reinterpret_cast<const float4*>(x + (size_t)t * 4);
    __nv_bfloat16 h0, h1, h2, h3, l0, l1, l2, l3;
    split_bf16(v.x, h0, l0); split_bf16(v.y, h1, l1);
    split_bf16(v.z, h2, l2); split_bf16(v.w, h3, l3);
    size_t off = (size_t)t * 4;
    reinterpret_cast<__nv_bfloat162*>(g_xh + off)[0] = __nv_bfloat162(h0, h1);
    reinterpret_cast<__nv_bfloat162*>(g_xh + off)[1] = __nv_bfloat162(h2, h3);
    reinterpret_cast<__nv_bfloat162*>(g_xl + off)[0] = __nv_bfloat162(l0, l1);
    reinterpret_cast<__nv_bfloat162*>(g_xl + off)[1] = __nv_bfloat162(l2, l3);
}

// ---------------- weight transpose + split ----------------
__global__ void k_wconv_e(const float* __restrict__ we) {
    int k = blockIdx.x;
    int n = threadIdx.x;
    __nv_bfloat16 hi, lo;
    split_bf16(we[k * HID + n], hi, lo);
    g_weh[n * IN_CH + k] = hi;
    g_wel[n * IN_CH + k] = lo;
}
__global__ void k_wconv(const float* __restrict__ wl, const float* __restrict__ wr) {
    int k = blockIdx.x;
    int n = threadIdx.x;
    float a = wl[k * HID + n];
    float b = wr[k * HID + n];
    __nv_bfloat16 hi, lo;
    split_bf16(a, hi, lo);
    g_wlh[n * HID + k] = hi; g_wll[n * HID + k] = lo;
    split_bf16(b, hi, lo);
    g_wrh[n * HID + k] = hi; g_wrl[n * HID + k] = lo;
}

// ---------------- batch -> int, pooled zero ----------------
__global__ void k_bi(const void* __restrict__ batch) {
    int v = blockIdx.x * 256 + threadIdx.x;
    if (v >= NN) return;
    int g = load_idx(batch, v, g_b64);
    if (g < 0) g = 0;
    if (g >= NG) g = NG - 1;
    g_bi[v] = g;
}
__global__ void k_zpool() {
    g_pooled[blockIdx.x * 256 + threadIdx.x] = 0.f;
}

// ---------------- CSR build ----------------
__global__ void k_zero_deg() {
    int i = blockIdx.x * 256 + threadIdx.x;
    if (i < NN) g_deg[i] = 0;
}
__global__ void k_count(const void* __restrict__ ei) {
    int e = blockIdx.x * 256 + threadIdx.x;
    if (e < NE) {
        int d = load_idx(ei, NE + e, g_ei64);
        if ((unsigned)d < NN) atomicAdd(&g_deg[d], 1);
    }
}
__global__ void k_scan1() {
    __shared__ int ws[256];
    int t = threadIdx.x;
    int i0 = blockIdx.x * 1024 + t * 4;
    int v0 = g_deg[i0], v1 = g_deg[i0 + 1], v2 = g_deg[i0 + 2], v3 = g_deg[i0 + 3];
    int sum = v0 + v1 + v2 + v3;
    ws[t] = sum;
    __syncthreads();
#pragma unroll
    for (int off = 1; off < 256; off <<= 1) {
        int x = (t >= off) ? ws[t - off] : 0;
        __syncthreads();
        ws[t] += x;
        __syncthreads();
    }
    int excl = ws[t] - sum;
    g_rowstart[i0]     = excl;
    g_rowstart[i0 + 1] = excl + v0;
    g_rowstart[i0 + 2] = excl + v0 + v1;
    g_rowstart[i0 + 3] = excl + v0 + v1 + v2;
    if (t == 255) g_blocksum[blockIdx.x] = ws[255];
}
__global__ void k_scan2() {
    __shared__ int ws[256];
    int t = threadIdx.x;
    int v = g_blocksum[t];
    ws[t] = v;
    __syncthreads();
#pragma unroll
    for (int off = 1; off < 256; off <<= 1) {
        int x = (t >= off) ? ws[t - off] : 0;
        __syncthreads();
        ws[t] += x;
        __syncthreads();
    }
    g_blockoff[t] = ws[t] - v;
}
__global__ void k_scan3() {
    int i = blockIdx.x * 256 + threadIdx.x;
    if (i >= NN) return;
    int rs = g_rowstart[i] + g_blockoff[i >> 10];
    g_rowstart[i] = rs;
    g_cursor[i] = rs;
    g_invdeg[i] = 1.0f / fmaxf((float)g_deg[i], 1.0f);
    if (i == 0) g_rowstart[NN] = NE;
}
__global__ void k_fill(const void* __restrict__ ei) {
    int e = blockIdx.x * 256 + threadIdx.x;
    if (e < NE) {
        int is64 = g_ei64;
        int d = load_idx(ei, NE + e, is64);
        int s = load_idx(ei, e, is64);
        if ((unsigned)d < NN && (unsigned)s < NN) {
            int pos = atomicAdd(&g_cursor[d], 1);
            if ((unsigned)pos < NE) g_csr[pos] = s;
        }
    }
}

// ---------------- mean aggregation ----------------
__global__ void k_aggregate(int sel) {
    const __nv_bfloat16* __restrict__ hh = g_hbh[sel];
    const __nv_bfloat16* __restrict__ hl = g_hbl[sel];
    int node = blockIdx.x * 4 + (threadIdx.x >> 6);
    int lane = threadIdx.x & 63;
    int s = g_rowstart[node], e = g_rowstart[node + 1];
    float a0 = 0.f, a1 = 0.f, a2 = 0.f, a3 = 0.f;
    for (int i = s; i < e; ++i) {
        int u = g_csr[i];
        size_t off = (size_t)u * HID + lane * 4;
        uint2 vh = *reinterpret_cast<const uint2*>(hh + off);
        uint2 vl = *reinterpret_cast<const uint2*>(hl + off);
        float2 h01 = __bfloat1622float2(*reinterpret_cast<__nv_bfloat162*>(&vh.x));
        float2 h23 = __bfloat1622float2(*reinterpret_cast<__nv_bfloat162*>(&vh.y));
        float2 l01 = __bfloat1622float2(*reinterpret_cast<__nv_bfloat162*>(&vl.x));
        float2 l23 = __bfloat1622float2(*reinterpret_cast<__nv_bfloat162*>(&vl.y));
        a0 += h01.x + l01.x; a1 += h01.y + l01.y;
        a2 += h23.x + l23.x; a3 += h23.y + l23.y;
    }
    float sc = g_invdeg[node];
    a0 *= sc; a1 *= sc; a2 *= sc; a3 *= sc;
    __nv_bfloat16 h0, h1, h2, h3, l0, l1, l2, l3;
    split_bf16(a0, h0, l0); split_bf16(a1, h1, l1);
    split_bf16(a2, h2, l2); split_bf16(a3, h3, l3);
    size_t off = (size_t)node * HID + lane * 4;
    __nv_bfloat162* ph = reinterpret_cast<__nv_bfloat162*>(g_aggh + off);
    ph[0] = __nv_bfloat162(h0, h1); ph[1] = __nv_bfloat162(h2, h3);
    __nv_bfloat162* pl = reinterpret_cast<__nv_bfloat162*>(g_aggl + off);
    pl[0] = __nv_bfloat162(l0, l1); pl[1] = __nv_bfloat162(l2, l3);
}

// ---------------- HMMA GEMM (bf16-split, 3-term), CTA tile 128x256 ----------------
#define ROWPITCH 80
#define A_TILE_B (128 * ROWPITCH)
#define W_TILE_B (256 * ROWPITCH)
#define STAGE_B (2 * A_TILE_B + 2 * W_TILE_B)
#define NSTAGE 3
#define SMEM_GEMM (NSTAGE * STAGE_B)            // 184320
#define EPIPITCH 528
#define EPITILE (128 * EPIPITCH)                // 67584

__global__ __launch_bounds__(512, 1)
void k_gemm(const float* __restrict__ bias, int mode, int hsel, int dst,
            int relu, int dopool) {
    extern __shared__ char smem[];
    const uint32_t sb = smem_u32(smem);
    const int tid = threadIdx.x;
    const int lane = tid & 31;
    const int wid = tid >> 5;
    const int wm = wid >> 3, wn = wid & 7;
    const int row0 = blockIdx.x * 128;

    const int nchunks = (mode == 0) ? 2 : 16;

    float acc[4][4][4];
#pragma unroll
    for (int i = 0; i < 4; i++)
#pragma unroll
        for (int j = 0; j < 4; j++)
#pragma unroll
            for (int q = 0; q < 4; q++) acc[i][j][q] = 0.f;

    auto issue = [&](int chunk, int buf) {
        const __nv_bfloat16 *Ah, *Al, *Wh, *Wl;
        int lda, kc;
        if (mode == 0) {
            Ah = g_xh; Al = g_xl; Wh = g_weh; Wl = g_wel;
            lda = IN_CH; kc = chunk;
        } else {
            if (chunk < 8) { Ah = g_aggh;      Al = g_aggl;      Wh = g_wlh; Wl = g_wll; }
            else           { Ah = g_hbh[hsel]; Al = g_hbl[hsel]; Wh = g_wrh; Wl = g_wrl; }
            lda = HID; kc = chunk & 7;
        }
        const uint32_t dbase = sb + buf * STAGE_B;
#pragma unroll
        for (int j = 0; j < 6; j++) {
            int u = tid + j * 512;
            const __nv_bfloat16* src;
            uint32_t dmat;
            int row, unit;
            if (u < 1024) {
                int arr = u >> 9, idx = u & 511;
                row = idx >> 2; unit = idx & 3;
                dmat = arr * A_TILE_B;
                src = (arr ? Al : Ah) + (size_t)(row0 + row) * lda + kc * 32 + unit * 8;
            } else {
                int v = u - 1024;
                int arr = v >> 10, idx = v & 1023;
                row = idx >> 2; unit = idx & 3;
                dmat = 2 * A_TILE_B + arr * W_TILE_B;
                src = (arr ? Wl : Wh) + (size_t)row * lda + kc * 32 + unit * 8;
            }
            CP_ASYNC16(dbase + dmat + row * ROWPITCH + unit * 16, (const char*)src);
        }
        CP_COMMIT();
    };

    for (int s = 0; s < NSTAGE - 1 && s < nchunks; ++s) issue(s, s);

    for (int chunk = 0; chunk < nchunks; ++chunk) {
        const int buf = chunk % NSTAGE;
        if (chunk + 1 < nchunks) CP_WAIT1(); else CP_WAIT0();
        __syncthreads();
        if (chunk + NSTAGE - 1 < nchunks)
            issue(chunk + NSTAGE - 1, (chunk + NSTAGE - 1) % NSTAGE);

        const uint32_t ah_b = sb + buf * STAGE_B;
        const uint32_t al_b = ah_b + A_TILE_B;
        const uint32_t wh_b = ah_b + 2 * A_TILE_B;
        const uint32_t wl_b = wh_b + W_TILE_B;

#pragma unroll
        for (int ks = 0; ks < 2; ++ks) {
            uint32_t ahf[4][4], alf[4][4];
            const uint32_t aoff = (lane & 15) * ROWPITCH + (lane >> 4) * 16 + ks * 32;
#pragma unroll
            for (int mt = 0; mt < 4; mt++) {
                uint32_t ad = (wm * 64 + mt * 16) * ROWPITCH + aoff;
                ldsm_x4(ahf[mt], ah_b + ad);
                ldsm_x4(alf[mt], al_b + ad);
            }
            const uint32_t woff = ((lane >> 4) * 8 + (lane & 7)) * ROWPITCH +
                                  ((lane >> 3) & 1) * 16 + ks * 32;
#pragma unroll
            for (int pair = 0; pair < 2; pair++) {
                uint32_t whf[4], wlf[4];
                uint32_t wd = (wn * 32 + pair * 16) * ROWPITCH + woff;
                ldsm_x4(whf, wh_b + wd);
                ldsm_x4(wlf, wl_b + wd);
#pragma unroll
                for (int mt = 0; mt < 4; mt++) {
#pragma unroll
                    for (int half = 0; half < 2; half++) {
                        int nt = pair * 2 + half;
                        float* c = acc[mt][nt];
                        mma_bf16(c[0], c[1], c[2], c[3], ahf[mt], &whf[half * 2]);
                        mma_bf16(c[0], c[1], c[2], c[3], ahf[mt], &wlf[half * 2]);
                        mma_bf16(c[0], c[1], c[2], c[3], alf[mt], &whf[half * 2]);
                    }
                }
            }
        }
    }
    __syncthreads();   // mainloop smem dead; safe to reuse

    if (dopool) {
        // fused global_add_pool: sum rows by graph into smem, flush with atomics
        float* pool = reinterpret_cast<float*>(smem);   // up to [32][256]
        const int glo = g_bi[row0];
        const int ghi = g_bi[row0 + 127];
        const int span = ghi - glo + 1;
        const bool direct = (span > 32);
        if (!direct) {
            for (int i = tid; i < span * HID; i += 512) pool[i] = 0.f;
        }
        __syncthreads();
#pragma unroll
        for (int mt = 0; mt < 4; mt++) {
            int rl_lo = wm * 64 + mt * 16 + (lane >> 2);
#pragma unroll
            for (int nt = 0; nt < 4; nt++) {
                int col = wn * 32 + nt * 8 + (lane & 3) * 2;
                float b0 = bias[col], b1 = bias[col + 1];
#pragma unroll
                for (int hh = 0; hh < 2; hh++) {
                    int rl = rl_lo + hh * 8;
                    int g = g_bi[row0 + rl];
                    float x0 = acc[mt][nt][hh * 2 + 0] + b0;
                    float x1 = acc[mt][nt][hh * 2 + 1] + b1;
                    if (!direct) {
                        atomicAdd(&pool[(g - glo) * HID + col], x0);
                        atomicAdd(&pool[(g - glo) * HID + col + 1], x1);
                    } else {
                        atomicAdd(&g_pooled[g * HID + col], x0);
                        atomicAdd(&g_pooled[g * HID + col + 1], x1);
                    }
                }
            }
        }
        __syncthreads();
        if (!direct) {
            for (int i = tid; i < span * HID; i += 512)
                atomicAdd(&g_pooled[glo * HID + i], pool[i]);
        }
        return;
    }

    // staged epilogue: acc -> smem bf16 tiles (conflict-free) -> coalesced 16B stores
#pragma unroll
    for (int mt = 0; mt < 4; mt++) {
        int rl_lo = wm * 64 + mt * 16 + (lane >> 2);
#pragma unroll
        for (int nt = 0; nt < 4; nt++) {
            int col = wn * 32 + nt * 8 + (lane & 3) * 2;
            float b0 = bias[col], b1 = bias[col + 1];
#pragma unroll
            for (int hh = 0; hh < 2; hh++) {
                int rl = rl_lo + hh * 8;
                float x0 = acc[mt][nt][hh * 2 + 0] + b0;
                float x1 = acc[mt][nt][hh * 2 + 1] + b1;
                if (relu) {
                    x0 = (x0 > 0.f) ? x0 : SLOPE * x0;
                    x1 = (x1 > 0.f) ? x1 : SLOPE * x1;
                }
                __nv_bfloat16 h0, h1, l0, l1;
                split_bf16(x0, h0, l0);
                split_bf16(x1, h1, l1);
                *reinterpret_cast<__nv_bfloat162*>(smem + rl * EPIPITCH + col * 2) =
                    __nv_bfloat162(h0, h1);
                *reinterpret_cast<__nv_bfloat162*>(smem + EPITILE + rl * EPIPITCH + col * 2) =
                    __nv_bfloat162(l0, l1);
            }
        }
    }
    __syncthreads();
    __nv_bfloat16* Ch = g_hbh[dst];
    __nv_bfloat16* Cl = g_hbl[dst];
#pragma unroll
    for (int i = tid; i < 128 * 32; i += 512) {
        int row = i >> 5, u = i & 31;
        uint4 vh = *reinterpret_cast<uint4*>(smem + row * EPIPITCH + u * 16);
        uint4 vl = *reinterpret_cast<uint4*>(smem + EPITILE + row * EPIPITCH + u * 16);
        *reinterpret_cast<uint4*>(
            reinterpret_cast<char*>(Ch + (size_t)(row0 + row) * HID) + u * 16) = vh;
        *reinterpret_cast<uint4*>(
            reinterpret_cast<char*>(Cl + (size_t)(row0 + row) * HID) + u * 16) = vl;
    }
}

// ---------------- fused head MLP ----------------
#define GPB 16
__global__ void k_head(const float* __restrict__ w1, const float* __restrict__ b1,
                       const float* __restrict__ w2, const float* __restrict__ b2,
                       float* __restrict__ out) {
    __shared__ float s[GPB][HID];
    __shared__ float red[256];
    int g0 = blockIdx.x * GPB;
    int j = threadIdx.x;
#pragma unroll
    for (int g = 0; g < GPB; ++g) s[g][j] = g_pooled[(g0 + g) * HID + j];
    __syncthreads();

    float acc[GPB];
#pragma unroll
    for (int g = 0; g < GPB; ++g) acc[g] = 0.f;
    for (int k = 0; k < HID; ++k) {
        float w = w1[k * HID + j];
#pragma unroll
        for (int g = 0; g < GPB; ++g) acc[g] = fmaf(s[g][k], w, acc[g]);
    }
    float bb = b1[j];
    float wj = w2[j];
#pragma unroll
    for (int g = 0; g < GPB; ++g) {
        float hj = acc[g] + bb;
        hj = (hj > 0.f) ? hj : SLOPE * hj;
        acc[g] = hj * wj;
    }
    for (int g = 0; g < GPB; ++g) {
        red[j] = acc[g];
        __syncthreads();
        for (int off = 128; off > 0; off >>= 1) {
            if (j < off) red[j] += red[j + off];
            __syncthreads();
        }
        if (j == 0) out[g0 + g] = red[0] + b2[0];
        __syncthreads();
    }
}

// ---------------- launch ----------------
extern "C" void kernel_launch(void* const* d_in, const int* in_sizes, int n_in,
                              void* d_out, int out_size) {
    const float* x       = (const float*)d_in[0];
    const void*  ei      = d_in[1];
    const void*  batch   = d_in[2];
    const float* embed_w = (const float*)d_in[3];
    const float* embed_b = (const float*)d_in[4];
    const float* lin_l_w = (const float*)d_in[5];
    const float* lin_l_b = (const float*)d_in[6];
    const float* lin_r_w = (const float*)d_in[7];
    const float* lin1_w  = (const float*)d_in[8];
    const float* lin1_b  = (const float*)d_in[9];
    const float* lin2_w  = (const float*)d_in[10];
    const float* lin2_b  = (const float*)d_in[11];
    float* out = (float*)d_out;

    cudaFuncSetAttribute(k_gemm, cudaFuncAttributeMaxDynamicSharedMemorySize, SMEM_GEMM);

    k_detect<<<1, 32>>>((const int*)ei, (const int*)batch);
    k_xsplit<<<NN * IN_CH / 4 / 256, 256>>>(x);
    k_wconv_e<<<IN_CH, HID>>>(embed_w);
    k_gemm<<<NN / 128, 512, SMEM_GEMM>>>(embed_b, 0, 0, 0, 0, 0);

    k_bi<<<NN / 256, 256>>>(batch);
    k_zpool<<<NG, 256>>>();

    // CSR build
    k_zero_deg<<<NN / 256, 256>>>();
    k_count<<<NE / 256, 256>>>(ei);
    k_scan1<<<256, 256>>>();
    k_scan2<<<1, 256>>>();
    k_scan3<<<NN / 256, 256>>>();
    k_fill<<<NE / 256, 256>>>(ei);

    int cur = 0;
    for (int i = 0; i < 3; i++) {
        k_wconv<<<HID, HID>>>(lin_l_w + (size_t)i * HID * HID,
                              lin_r_w + (size_t)i * HID * HID);
        k_aggregate<<<NN / 4, 256>>>(cur);
        int last = (i == 2);
        k_gemm<<<NN / 128, 512, SMEM_GEMM>>>(lin_l_b + (size_t)i * HID, 1, cur,
                                             1 - cur, last ? 0 : 1, last);
        cur = 1 - cur;
    }

    k_head<<<NG / GPB, 256>>>(lin1_w, lin1_b, lin2_w, lin2_b, out);
}